// round 1
// baseline (speedup 1.0000x reference)
#include <cuda_runtime.h>
#include <cuda_bf16.h>
#include <cstdint>

#define BB 16
#define NN 4096
#define SS 1024
#define KK 32
#define DD 64
#define C0 67
#define C1 64
#define C2 64
#define C3 128

// ---------------- device scratch (no allocations allowed) ----------------
__device__ float g_W0[C0*C1];
__device__ float g_b0[C1];
__device__ float g_W1[C1*C2];
__device__ float g_b1[C2];
__device__ float g_W2[C2*C3];
__device__ float g_b2[C3];
__device__ int   g_idx[BB*SS*KK];

// ---------------- fold BN into conv weights ----------------
__global__ void fold_kernel(const float* __restrict__ W0, const float* __restrict__ b0,
                            const float* __restrict__ g0, const float* __restrict__ be0,
                            const float* __restrict__ m0, const float* __restrict__ v0,
                            const float* __restrict__ W1, const float* __restrict__ b1,
                            const float* __restrict__ g1, const float* __restrict__ be1,
                            const float* __restrict__ m1, const float* __restrict__ v1,
                            const float* __restrict__ W2, const float* __restrict__ b2,
                            const float* __restrict__ g2, const float* __restrict__ be2,
                            const float* __restrict__ m2, const float* __restrict__ v2) {
    int o = threadIdx.x;
    if (o < C1) {
        float s = g0[o] * rsqrtf(v0[o] + 1e-5f);
        g_b0[o] = (b0[o] - m0[o]) * s + be0[o];
        for (int c = 0; c < C0; c++) g_W0[c*C1+o] = W0[c*C1+o] * s;
    }
    if (o < C2) {
        float s = g1[o] * rsqrtf(v1[o] + 1e-5f);
        g_b1[o] = (b1[o] - m1[o]) * s + be1[o];
        for (int c = 0; c < C1; c++) g_W1[c*C2+o] = W1[c*C2+o] * s;
    }
    if (o < C3) {
        float s = g2[o] * rsqrtf(v2[o] + 1e-5f);
        g_b2[o] = (b2[o] - m2[o]) * s + be2[o];
        for (int c = 0; c < C2; c++) g_W2[c*C3+o] = W2[c*C3+o] * s;
    }
}

// ---------------- farthest point sampling ----------------
#define FPS_T 512
#define PPT   8   // points per thread: 512*8 = 4096

__global__ __launch_bounds__(FPS_T) void fps_kernel(const float* __restrict__ xyz,
                                                    float* __restrict__ new_xyz) {
    int b = blockIdx.x;
    const float* Xp = xyz + (size_t)b * NN * 3;
    __shared__ float cent[3];
    __shared__ float swv[16], swx[16], swy[16], swz[16];
    __shared__ int   swi[16];
    int t = threadIdx.x;

    float px[PPT], py[PPT], pz[PPT], md[PPT];
#pragma unroll
    for (int i = 0; i < PPT; i++) {
        int p = t + i * FPS_T;
        px[i] = Xp[p*3+0]; py[i] = Xp[p*3+1]; pz[i] = Xp[p*3+2];
        md[i] = 1e10f;
    }
    if (t == 0) {
        cent[0] = px[0]; cent[1] = py[0]; cent[2] = pz[0];
        new_xyz[(size_t)(b*SS)*3+0] = px[0];
        new_xyz[(size_t)(b*SS)*3+1] = py[0];
        new_xyz[(size_t)(b*SS)*3+2] = pz[0];
    }
    __syncthreads();

    for (int it = 1; it < SS; it++) {
        float cx = cent[0], cy = cent[1], cz = cent[2];
        float bv = -1.0f, bx = 0.f, by = 0.f, bz = 0.f;
        int bi = NN;
#pragma unroll
        for (int i = 0; i < PPT; i++) {
            float dx = px[i]-cx, dy = py[i]-cy, dz = pz[i]-cz;
            // exact op order, no FMA contraction: (dx^2 + dy^2) + dz^2
            float d = __fadd_rn(__fadd_rn(__fmul_rn(dx,dx), __fmul_rn(dy,dy)), __fmul_rn(dz,dz));
            float m = fminf(md[i], d);
            md[i] = m;
            int p = t + i*FPS_T;
            bool take = (m > bv) || (m == bv && p < bi);
            if (take) { bv = m; bi = p; bx = px[i]; by = py[i]; bz = pz[i]; }
        }
#pragma unroll
        for (int off = 16; off > 0; off >>= 1) {
            float ov = __shfl_xor_sync(0xffffffffu, bv, off);
            int   oi = __shfl_xor_sync(0xffffffffu, bi, off);
            float ox = __shfl_xor_sync(0xffffffffu, bx, off);
            float oy = __shfl_xor_sync(0xffffffffu, by, off);
            float oz = __shfl_xor_sync(0xffffffffu, bz, off);
            bool take = (ov > bv) || (ov == bv && oi < bi);
            if (take) { bv = ov; bi = oi; bx = ox; by = oy; bz = oz; }
        }
        int w = t >> 5;
        if ((t & 31) == 0) { swv[w]=bv; swi[w]=bi; swx[w]=bx; swy[w]=by; swz[w]=bz; }
        __syncthreads();
        if (t < 32) {
            bool valid = t < 16;
            bv = valid ? swv[t] : -1.0f;
            bi = valid ? swi[t] : NN;
            bx = valid ? swx[t] : 0.f;
            by = valid ? swy[t] : 0.f;
            bz = valid ? swz[t] : 0.f;
#pragma unroll
            for (int off = 8; off > 0; off >>= 1) {
                float ov = __shfl_xor_sync(0xffffffffu, bv, off);
                int   oi = __shfl_xor_sync(0xffffffffu, bi, off);
                float ox = __shfl_xor_sync(0xffffffffu, bx, off);
                float oy = __shfl_xor_sync(0xffffffffu, by, off);
                float oz = __shfl_xor_sync(0xffffffffu, bz, off);
                bool take = (ov > bv) || (ov == bv && oi < bi);
                if (take) { bv = ov; bi = oi; bx = ox; by = oy; bz = oz; }
            }
            if (t == 0) {
                cent[0] = bx; cent[1] = by; cent[2] = bz;
                float* op = new_xyz + (size_t)(b*SS + it)*3;
                op[0] = bx; op[1] = by; op[2] = bz;
            }
        }
        __syncthreads();
    }
}

// ---------------- ball query: first K in index order within radius ----------------
__global__ __launch_bounds__(256) void ballquery_kernel(const float* __restrict__ xyz,
                                                        const float* __restrict__ new_xyz) {
    int gw   = (int)((blockIdx.x * blockDim.x + threadIdx.x) >> 5);
    int lane = threadIdx.x & 31;
    if (gw >= BB*SS) return;
    int b = gw >> 10;  // SS = 1024
    const float* Xp = xyz + (size_t)b * NN * 3;
    float cx = new_xyz[(size_t)gw*3+0];
    float cy = new_xyz[(size_t)gw*3+1];
    float cz = new_xyz[(size_t)gw*3+2];
    const float R2 = (float)(0.2 * 0.2);  // double-computed then truncated, matches JAX
    int* outp = g_idx + (size_t)gw * KK;
    int found = 0;
    for (int base = 0; base < NN && found < KK; base += 32) {
        int p = base + lane;
        float dx = Xp[p*3+0]-cx, dy = Xp[p*3+1]-cy, dz = Xp[p*3+2]-cz;
        float d2 = __fadd_rn(__fadd_rn(__fmul_rn(dx,dx), __fmul_rn(dy,dy)), __fmul_rn(dz,dz));
        bool pred = d2 < R2;
        unsigned m = __ballot_sync(0xffffffffu, pred);
        int pos = __popc(m & ((1u << lane) - 1u));
        if (pred && found + pos < KK) outp[found + pos] = p;
        found += __popc(m);
    }
    if (found > KK) found = KK;
    for (int j = found + lane; j < KK; j += 32) outp[j] = -1;
}

// ---------------- fused gather + 3-layer MLP + maxpool ----------------
// One block handles 2 centroids (64 "rows": 2 x 32 neighbors).
// X in shared as [c][k] (stride 68) so both operands of the FMA loop are float4 LDS.
#define MT 256
#define XSTR 68

__global__ __launch_bounds__(MT) void mlp_kernel(const float* __restrict__ xyz,
                                                 const float* __restrict__ points,
                                                 const float* __restrict__ new_xyz,
                                                 float* __restrict__ out_np) {
    extern __shared__ float sm[];
    float* sW0 = sm;                 // 4288
    float* sW1 = sW0 + C0*C1;        // 4096
    float* sW2 = sW1 + C1*C2;        // 8192
    float* sb0 = sW2 + C2*C3;        // 64
    float* sb1 = sb0 + C1;           // 64
    float* sb2 = sb1 + C2;           // 128
    float* sX  = sb2 + C3;           // 67*68
    float* sH  = sX + C0*XSTR;       // 64*68
    int*   sMax  = (int*)(sH + C1*XSTR);  // 2*128
    int*   sIdx  = sMax + 2*C3;           // 64
    float* sCent = (float*)(sIdx + 2*KK); // 6

    int t   = threadIdx.x;
    int bid = blockIdx.x;
    int b   = bid >> 9;            // 512 centroid-pairs per batch
    int s0  = (bid & 511) * 2;

    if (t < 2*KK) sIdx[t] = g_idx[((size_t)(b*SS + s0))*KK + t];
    if (t < 6)    sCent[t] = new_xyz[(size_t)(b*SS + s0)*3 + t];
    sMax[t] = 0;   // post-ReLU values are >= 0, so 0 is the max identity
    __syncthreads();

    // stage folded weights (L2-resident, coalesced)
    for (int e = t; e < C0*C1; e += MT) sW0[e] = g_W0[e];
    for (int e = t; e < C1*C2; e += MT) sW1[e] = g_W1[e];
    for (int e = t; e < C2*C3; e += MT) sW2[e] = g_W2[e];
    if (t < C1) sb0[t] = g_b0[t];
    if (t < C2) sb1[t] = g_b1[t];
    if (t < C3) sb2[t] = g_b2[t];

    // gather X: xyz part (c = 0..2), normalized by centroid; idx=-1 -> 0 - cent
    for (int e = t; e < 3*64; e += MT) {
        int c = e >> 6, kk = e & 63;
        int cl = kk >> 5;
        int id = sIdx[kk];
        float v = (id < 0) ? 0.0f : xyz[((size_t)b*NN + id)*3 + c];
        sX[c*XSTR + kk] = v - sCent[cl*3 + c];
    }
    // points part (c = 3..66); idx=-1 wraps to row N-1 (torch semantics)
    for (int e = t; e < 64*64; e += MT) {
        int kk = e >> 6, c = e & 63;  // consecutive lanes -> consecutive c: coalesced
        int id = sIdx[kk];
        int pid = (id < 0) ? (NN-1) : id;
        sX[(3+c)*XSTR + kk] = points[((size_t)b*NN + pid)*DD + c];
    }
    __syncthreads();

    // ----- Layer 1: 67 -> 64.  thread: 4 k (kg=t>>4), 4 out (og=t&15) -----
    {
        int kb = (t >> 4) * 4, ob = (t & 15) * 4;
        float acc[4][4];
#pragma unroll
        for (int i = 0; i < 4; i++)
#pragma unroll
            for (int j = 0; j < 4; j++) acc[i][j] = 0.0f;
        for (int c = 0; c < C0; c++) {
            float4 xv = *(const float4*)&sX[c*XSTR + kb];
            float4 wv = *(const float4*)&sW0[c*C1 + ob];
            float xs[4] = {xv.x, xv.y, xv.z, xv.w};
            float ws[4] = {wv.x, wv.y, wv.z, wv.w};
#pragma unroll
            for (int i = 0; i < 4; i++)
#pragma unroll
                for (int j = 0; j < 4; j++) acc[i][j] += xs[i] * ws[j];
        }
#pragma unroll
        for (int j = 0; j < 4; j++) {
            float bb = sb0[ob + j];
#pragma unroll
            for (int i = 0; i < 4; i++)
                sH[(ob + j)*XSTR + kb + i] = fmaxf(acc[i][j] + bb, 0.0f);
        }
    }
    __syncthreads();

    // ----- Layer 2: 64 -> 64.  sH -> sX (reuse) -----
    {
        int kb = (t >> 4) * 4, ob = (t & 15) * 4;
        float acc[4][4];
#pragma unroll
        for (int i = 0; i < 4; i++)
#pragma unroll
            for (int j = 0; j < 4; j++) acc[i][j] = 0.0f;
        for (int c = 0; c < C1; c++) {
            float4 xv = *(const float4*)&sH[c*XSTR + kb];
            float4 wv = *(const float4*)&sW1[c*C2 + ob];
            float xs[4] = {xv.x, xv.y, xv.z, xv.w};
            float ws[4] = {wv.x, wv.y, wv.z, wv.w};
#pragma unroll
            for (int i = 0; i < 4; i++)
#pragma unroll
                for (int j = 0; j < 4; j++) acc[i][j] += xs[i] * ws[j];
        }
        __syncthreads();  // all L2 reads of sH done before overwriting sX? (sX is input of L1, free now)
#pragma unroll
        for (int j = 0; j < 4; j++) {
            float bb = sb1[ob + j];
#pragma unroll
            for (int i = 0; i < 4; i++)
                sX[(ob + j)*XSTR + kb + i] = fmaxf(acc[i][j] + bb, 0.0f);
        }
    }
    __syncthreads();

    // ----- Layer 3: 64 -> 128, fused maxpool.  thread: 8 k (kg=t>>5), 4 out (og=t&31) -----
    {
        int kb = (t >> 5) * 8, ob = (t & 31) * 4;
        float acc[8][4];
#pragma unroll
        for (int i = 0; i < 8; i++)
#pragma unroll
            for (int j = 0; j < 4; j++) acc[i][j] = 0.0f;
        for (int c = 0; c < C2; c++) {
            float4 x0 = *(const float4*)&sX[c*XSTR + kb];
            float4 x1 = *(const float4*)&sX[c*XSTR + kb + 4];
            float4 wv = *(const float4*)&sW2[c*C3 + ob];
            float xs[8] = {x0.x, x0.y, x0.z, x0.w, x1.x, x1.y, x1.z, x1.w};
            float ws[4] = {wv.x, wv.y, wv.z, wv.w};
#pragma unroll
            for (int i = 0; i < 8; i++)
#pragma unroll
                for (int j = 0; j < 4; j++) acc[i][j] += xs[i] * ws[j];
        }
        int cl = kb >> 5;   // this thread's 8 k are within one centroid
#pragma unroll
        for (int j = 0; j < 4; j++) {
            float bb = sb2[ob + j];
            float mx = 0.0f;
#pragma unroll
            for (int i = 0; i < 8; i++)
                mx = fmaxf(mx, fmaxf(acc[i][j] + bb, 0.0f));
            atomicMax(&sMax[cl*C3 + ob + j], __float_as_int(mx));
        }
    }
    __syncthreads();

    {
        int cl = t >> 7, o = t & 127;
        out_np[((size_t)(b*SS + s0 + cl))*C3 + o] = __int_as_float(sMax[cl*C3 + o]);
    }
}

// ---------------- launch ----------------
static const size_t MLP_SMEM =
    (size_t)(C0*C1 + C1*C2 + C2*C3 + C1 + C2 + C3 + C0*XSTR + C1*XSTR) * 4
    + (size_t)(2*C3 + 2*KK) * 4 + 6*4 + 16;

extern "C" void kernel_launch(void* const* d_in, const int* in_sizes, int n_in,
                              void* d_out, int out_size) {
    const float* xyz    = (const float*)d_in[0];
    const float* points = (const float*)d_in[1];
    float* out        = (float*)d_out;
    float* new_xyz    = out;                        // B*S*3 floats
    float* new_points = out + (size_t)BB*SS*3;      // B*S*128 floats

    fold_kernel<<<1, 128>>>(
        (const float*)d_in[2],  (const float*)d_in[3],  (const float*)d_in[4],
        (const float*)d_in[5],  (const float*)d_in[6],  (const float*)d_in[7],
        (const float*)d_in[8],  (const float*)d_in[9],  (const float*)d_in[10],
        (const float*)d_in[11], (const float*)d_in[12], (const float*)d_in[13],
        (const float*)d_in[14], (const float*)d_in[15], (const float*)d_in[16],
        (const float*)d_in[17], (const float*)d_in[18], (const float*)d_in[19]);

    fps_kernel<<<BB, FPS_T>>>(xyz, new_xyz);

    ballquery_kernel<<<(BB*SS*32 + 255)/256, 256>>>(xyz, new_xyz);

    cudaFuncSetAttribute(mlp_kernel, cudaFuncAttributeMaxDynamicSharedMemorySize,
                         (int)MLP_SMEM);
    mlp_kernel<<<BB*SS/2, MT, MLP_SMEM>>>(xyz, points, new_xyz, new_points);
}

// round 5
// speedup vs baseline: 1.3205x; 1.3205x over previous
#include <cuda_runtime.h>
#include <cuda_bf16.h>
#include <cstdint>

#define BB 16
#define NN 4096
#define SS 1024
#define KK 32
#define DD 64
#define C0 67
#define C1 64
#define C2 64
#define C3 128
#define CP 260   // sX row stride in floats (multiple of 4, ≡4 mod 32 to limit bank conflicts)

// ---------------- device scratch ----------------
__device__ float g_W0[C0*C1];
__device__ float g_b0[C1];
__device__ float g_W1[C1*C2];
__device__ float g_b1[C2];
__device__ float g_W2[C2*C3];
__device__ float g_b2[C3];
__device__ int   g_idx[BB*SS*KK];

// ---------------- f32x2 helpers ----------------
__device__ __forceinline__ unsigned long long ffma2(unsigned long long a,
                                                    unsigned long long b,
                                                    unsigned long long c) {
    unsigned long long d;
    asm("fma.rn.f32x2 %0, %1, %2, %3;" : "=l"(d) : "l"(a), "l"(b), "l"(c));
    return d;
}
__device__ __forceinline__ unsigned long long splat2(float w) {
    unsigned long long d;
    asm("mov.b64 %0, {%1, %1};" : "=l"(d) : "f"(w));
    return d;
}
__device__ __forceinline__ void unpack2(unsigned long long v, float& lo, float& hi) {
    asm("mov.b64 {%0, %1}, %2;" : "=f"(lo), "=f"(hi) : "l"(v));
}
__device__ __forceinline__ unsigned redux_max_u32(unsigned v) {
    unsigned d;
    asm("redux.sync.max.u32 %0, %1, 0xffffffff;" : "=r"(d) : "r"(v));
    return d;
}
__device__ __forceinline__ unsigned redux_min_u32(unsigned v) {
    unsigned d;
    asm("redux.sync.min.u32 %0, %1, 0xffffffff;" : "=r"(d) : "r"(v));
    return d;
}

// ---------------- fold BN into conv weights ----------------
__global__ void fold_kernel(const float* __restrict__ W0, const float* __restrict__ b0,
                            const float* __restrict__ g0, const float* __restrict__ be0,
                            const float* __restrict__ m0, const float* __restrict__ v0,
                            const float* __restrict__ W1, const float* __restrict__ b1,
                            const float* __restrict__ g1, const float* __restrict__ be1,
                            const float* __restrict__ m1, const float* __restrict__ v1,
                            const float* __restrict__ W2, const float* __restrict__ b2,
                            const float* __restrict__ g2, const float* __restrict__ be2,
                            const float* __restrict__ m2, const float* __restrict__ v2) {
    int o = threadIdx.x;
    if (o < C1) {
        float s = g0[o] * rsqrtf(v0[o] + 1e-5f);
        g_b0[o] = (b0[o] - m0[o]) * s + be0[o];
        for (int c = 0; c < C0; c++) g_W0[c*C1+o] = W0[c*C1+o] * s;
    }
    if (o < C2) {
        float s = g1[o] * rsqrtf(v1[o] + 1e-5f);
        g_b1[o] = (b1[o] - m1[o]) * s + be1[o];
        for (int c = 0; c < C1; c++) g_W1[c*C2+o] = W1[c*C2+o] * s;
    }
    if (o < C3) {
        float s = g2[o] * rsqrtf(v2[o] + 1e-5f);
        g_b2[o] = (b2[o] - m2[o]) * s + be2[o];
        for (int c = 0; c < C2; c++) g_W2[c*C3+o] = W2[c*C3+o] * s;
    }
}

// ---------------- farthest point sampling ----------------
// 512 threads, 8 pts/thread, ONE barrier/iter (parity double-buffered scratch),
// redux-based argmax, xyz staged in smem for the centroid fetch.
#define FPS_T 512
#define PPT   8

__global__ __launch_bounds__(FPS_T) void fps_kernel(const float* __restrict__ xyz,
                                                    float* __restrict__ new_xyz) {
    extern __shared__ float fsm[];
    float*    sxyz = fsm;                       // NN*3 = 12288 floats (48KB)
    unsigned* swv  = (unsigned*)(sxyz + NN*3);  // [2][16]
    int*      swi  = (int*)(swv + 32);          // [2][16]

    int b = blockIdx.x;
    const float* Xp = xyz + (size_t)b * NN * 3;
    int t = threadIdx.x;
    int lane = t & 31, w = t >> 5;

    for (int e = t; e < NN*3; e += FPS_T) sxyz[e] = Xp[e];
    __syncthreads();

    float px[PPT], py[PPT], pz[PPT], md[PPT];
#pragma unroll
    for (int i = 0; i < PPT; i++) {
        int p = t + i * FPS_T;
        px[i] = sxyz[p*3+0]; py[i] = sxyz[p*3+1]; pz[i] = sxyz[p*3+2];
        md[i] = 1e10f;
    }
    float cx = sxyz[0], cy = sxyz[1], cz = sxyz[2];
    if (t == 0) {
        new_xyz[(size_t)(b*SS)*3+0] = cx;
        new_xyz[(size_t)(b*SS)*3+1] = cy;
        new_xyz[(size_t)(b*SS)*3+2] = cz;
    }

    int par = 0;
    for (int it = 1; it < SS; it++) {
        unsigned bv = 0;            // dist bits (dist >= 0 so int order == float order)
        int bi = 0x7fffffff;
#pragma unroll
        for (int i = 0; i < PPT; i++) {
            float dx = px[i]-cx, dy = py[i]-cy, dz = pz[i]-cz;
            // exact reference op order, no FMA contraction
            float d = __fadd_rn(__fadd_rn(__fmul_rn(dx,dx), __fmul_rn(dy,dy)), __fmul_rn(dz,dz));
            float m = fminf(md[i], d);
            md[i] = m;
            unsigned mb = __float_as_uint(m);
            int p = t + i*FPS_T;
            if (mb > bv || (mb == bv && p < bi)) { bv = mb; bi = p; }
        }
        unsigned vmax = redux_max_u32(bv);
        unsigned cand = (bv == vmax) ? (unsigned)bi : 0x7fffffffu;
        unsigned imin = redux_min_u32(cand);
        if (lane == 0) { swv[par*16 + w] = vmax; swi[par*16 + w] = (int)imin; }
        __syncthreads();
        // every thread does the 16-way reduce redundantly (no 2nd barrier needed:
        // next iteration writes the OTHER parity buffer)
        unsigned best = 0; int besti = 0x7fffffff;
#pragma unroll
        for (int w2 = 0; w2 < 16; w2++) {
            unsigned v = swv[par*16 + w2]; int ii = swi[par*16 + w2];
            if (v > best || (v == best && ii < besti)) { best = v; besti = ii; }
        }
        cx = sxyz[besti*3+0]; cy = sxyz[besti*3+1]; cz = sxyz[besti*3+2];
        if (t == 0) {
            float* op = new_xyz + (size_t)(b*SS + it)*3;
            op[0] = cx; op[1] = cy; op[2] = cz;
        }
        par ^= 1;
    }
}

// ---------------- ball query ----------------
__global__ __launch_bounds__(256) void ballquery_kernel(const float* __restrict__ xyz,
                                                        const float* __restrict__ new_xyz) {
    int gw   = (int)((blockIdx.x * blockDim.x + threadIdx.x) >> 5);
    int lane = threadIdx.x & 31;
    if (gw >= BB*SS) return;
    int b = gw >> 10;
    const float* Xp = xyz + (size_t)b * NN * 3;
    float cx = new_xyz[(size_t)gw*3+0];
    float cy = new_xyz[(size_t)gw*3+1];
    float cz = new_xyz[(size_t)gw*3+2];
    const float R2 = (float)(0.2 * 0.2);
    int* outp = g_idx + (size_t)gw * KK;
    int found = 0;
    for (int base = 0; base < NN && found < KK; base += 32) {
        int p = base + lane;
        float dx = Xp[p*3+0]-cx, dy = Xp[p*3+1]-cy, dz = Xp[p*3+2]-cz;
        float d2 = __fadd_rn(__fadd_rn(__fmul_rn(dx,dx), __fmul_rn(dy,dy)), __fmul_rn(dz,dz));
        bool pred = d2 < R2;
        unsigned m = __ballot_sync(0xffffffffu, pred);
        int pos = __popc(m & ((1u << lane) - 1u));
        if (pred && found + pos < KK) outp[found + pos] = p;
        found += __popc(m);
    }
    if (found > KK) found = KK;
    for (int j = found + lane; j < KK; j += 32) outp[j] = -1;
}

// ---------------- fused gather + 3-layer MLP + maxpool ----------------
// 8 centroids/block (256 points). X in smem [c][k] (stride CP). Weights via LDG
// (L1-cached, no staging). Thread tile: 8 k x 8 o with f32x2 packed FMA.
#define MT 256

// gemm tile: acc[i][j] over k-pairs i=0..3 (k = kb+2i,2i+1), outputs j=0..7
template<int CIN>
__device__ __forceinline__ void gemm_tile(const float* __restrict__ sX, int kb,
                                          const float* __restrict__ Wg, int wstride, int ob,
                                          unsigned long long acc[4][8]) {
#pragma unroll
    for (int i = 0; i < 4; i++)
#pragma unroll
        for (int j = 0; j < 8; j++) acc[i][j] = 0ull;
#pragma unroll 2
    for (int c = 0; c < CIN; c++) {
        ulonglong2 xa = *(const ulonglong2*)&sX[c*CP + kb];
        ulonglong2 xb = *(const ulonglong2*)&sX[c*CP + kb + 4];
        float4 w0 = __ldg((const float4*)&Wg[c*wstride + ob]);
        float4 w1 = __ldg((const float4*)&Wg[c*wstride + ob + 4]);
        unsigned long long xp[4] = {xa.x, xa.y, xb.x, xb.y};
        unsigned long long ws[8] = {splat2(w0.x), splat2(w0.y), splat2(w0.z), splat2(w0.w),
                                    splat2(w1.x), splat2(w1.y), splat2(w1.z), splat2(w1.w)};
#pragma unroll
        for (int i = 0; i < 4; i++)
#pragma unroll
            for (int j = 0; j < 8; j++) acc[i][j] = ffma2(xp[i], ws[j], acc[i][j]);
    }
}

__global__ __launch_bounds__(MT, 2) void mlp_kernel(const float* __restrict__ xyz,
                                                    const float* __restrict__ points,
                                                    const float* __restrict__ new_xyz,
                                                    float* __restrict__ out_np) {
    extern __shared__ float sm[];
    float* sX   = sm;                      // 67 * CP floats
    int*   sMax = (int*)(sX + C0*CP);      // 8*128
    int*   sIdx = sMax + 8*C3;             // 256
    float* sCent= (float*)(sIdx + 256);    // 24

    int t   = threadIdx.x;
    int bid = blockIdx.x;
    int b   = bid >> 7;            // 128 blocks per batch
    int s0  = (bid & 127) * 8;

    sIdx[t] = g_idx[((size_t)(b*SS + s0))*KK + t];
    if (t < 24) sCent[t] = new_xyz[(size_t)(b*SS + s0)*3 + t];
#pragma unroll
    for (int q = 0; q < 4; q++) sMax[t*4 + q] = 0;  // post-ReLU >= 0
    __syncthreads();

    // gather xyz part (c=0..2), normalized; idx=-1 -> 0 - cent
    for (int e = t; e < 3*256; e += MT) {
        int c = e >> 8, k = e & 255;
        int cl = k >> 5;
        int id = sIdx[k];
        float v = (id < 0) ? 0.0f : xyz[((size_t)b*NN + id)*3 + c];
        sX[c*CP + k] = v - sCent[cl*3 + c];
    }
    // points part (c=3..66); idx=-1 wraps to N-1
    for (int e = t; e < 256*16; e += MT) {
        int k = e >> 4, c4 = e & 15;
        int id = sIdx[k];
        int pid = (id < 0) ? (NN-1) : id;
        float4 p = *(const float4*)&points[((size_t)b*NN + pid)*DD + c4*4];
        sX[(3 + c4*4 + 0)*CP + k] = p.x;
        sX[(3 + c4*4 + 1)*CP + k] = p.y;
        sX[(3 + c4*4 + 2)*CP + k] = p.z;
        sX[(3 + c4*4 + 3)*CP + k] = p.w;
    }
    __syncthreads();

    int kb = (t >> 3) * 8;   // 32 k-groups of 8
    int ob = (t & 7) * 8;    // 8 o-groups of 8 (covers 64)
    unsigned long long acc[4][8];

    // ----- Layer 1: 67 -> 64 -----
    gemm_tile<C0>(sX, kb, g_W0, C1, ob, acc);
    __syncthreads();
#pragma unroll
    for (int j = 0; j < 8; j++) {
        int o = ob + j;
        float bb = __ldg(&g_b0[o]);
        float f[8];
#pragma unroll
        for (int i = 0; i < 4; i++) {
            float lo, hi; unpack2(acc[i][j], lo, hi);
            f[2*i]   = fmaxf(lo + bb, 0.0f);
            f[2*i+1] = fmaxf(hi + bb, 0.0f);
        }
        *(float4*)&sX[o*CP + kb]     = make_float4(f[0], f[1], f[2], f[3]);
        *(float4*)&sX[o*CP + kb + 4] = make_float4(f[4], f[5], f[6], f[7]);
    }
    __syncthreads();

    // ----- Layer 2: 64 -> 64 -----
    gemm_tile<C1>(sX, kb, g_W1, C2, ob, acc);
    __syncthreads();
#pragma unroll
    for (int j = 0; j < 8; j++) {
        int o = ob + j;
        float bb = __ldg(&g_b1[o]);
        float f[8];
#pragma unroll
        for (int i = 0; i < 4; i++) {
            float lo, hi; unpack2(acc[i][j], lo, hi);
            f[2*i]   = fmaxf(lo + bb, 0.0f);
            f[2*i+1] = fmaxf(hi + bb, 0.0f);
        }
        *(float4*)&sX[o*CP + kb]     = make_float4(f[0], f[1], f[2], f[3]);
        *(float4*)&sX[o*CP + kb + 4] = make_float4(f[4], f[5], f[6], f[7]);
    }
    __syncthreads();

    // ----- Layer 3: 64 -> 128 (two o-halves), fused maxpool -----
    int cent = kb >> 5;  // this thread's 8 k are within one centroid
#pragma unroll
    for (int h = 0; h < 2; h++) {
        gemm_tile<C2>(sX, kb, g_W2 + h*64, C3, ob, acc);
#pragma unroll
        for (int j = 0; j < 8; j++) {
            int o = h*64 + ob + j;
            float bb = __ldg(&g_b2[o]);
            float mx = 0.0f;
#pragma unroll
            for (int i = 0; i < 4; i++) {
                float lo, hi; unpack2(acc[i][j], lo, hi);
                mx = fmaxf(mx, fmaxf(lo + bb, 0.0f));
                mx = fmaxf(mx, fmaxf(hi + bb, 0.0f));
            }
            atomicMax(&sMax[cent*C3 + o], __float_as_int(mx));
        }
    }
    __syncthreads();

    for (int e = t; e < 8*C3; e += MT) {
        int cc = e >> 7, o = e & 127;
        out_np[((size_t)(b*SS + s0 + cc))*C3 + o] = __int_as_float(sMax[e]);
    }
}

// ---------------- launch ----------------
static const size_t MLP_SMEM = (size_t)(C0*CP)*4 + (size_t)(8*C3 + 256)*4 + 24*4 + 16;
static const size_t FPS_SMEM = (size_t)(NN*3)*4 + 32*4 + 32*4 + 16;

extern "C" void kernel_launch(void* const* d_in, const int* in_sizes, int n_in,
                              void* d_out, int out_size) {
    const float* xyz    = (const float*)d_in[0];
    const float* points = (const float*)d_in[1];
    float* out        = (float*)d_out;
    float* new_xyz    = out;
    float* new_points = out + (size_t)BB*SS*3;

    fold_kernel<<<1, 128>>>(
        (const float*)d_in[2],  (const float*)d_in[3],  (const float*)d_in[4],
        (const float*)d_in[5],  (const float*)d_in[6],  (const float*)d_in[7],
        (const float*)d_in[8],  (const float*)d_in[9],  (const float*)d_in[10],
        (const float*)d_in[11], (const float*)d_in[12], (const float*)d_in[13],
        (const float*)d_in[14], (const float*)d_in[15], (const float*)d_in[16],
        (const float*)d_in[17], (const float*)d_in[18], (const float*)d_in[19]);

    cudaFuncSetAttribute(fps_kernel, cudaFuncAttributeMaxDynamicSharedMemorySize,
                         (int)FPS_SMEM);
    fps_kernel<<<BB, FPS_T, FPS_SMEM>>>(xyz, new_xyz);

    ballquery_kernel<<<(BB*SS*32 + 255)/256, 256>>>(xyz, new_xyz);

    cudaFuncSetAttribute(mlp_kernel, cudaFuncAttributeMaxDynamicSharedMemorySize,
                         (int)MLP_SMEM);
    mlp_kernel<<<BB*SS/8, MT, MLP_SMEM>>>(xyz, points, new_xyz, new_points);
}

// round 14
// speedup vs baseline: 1.5036x; 1.1387x over previous
#include <cuda_runtime.h>
#include <cuda_bf16.h>
#include <cstdint>

#define BB 16
#define NN 4096
#define SS 1024
#define KK 32
#define DD 64
#define C0 67
#define C1 64
#define C2 64
#define C3 128
#define CP 260   // sX row stride in floats

// ---------------- device scratch ----------------
__device__ float g_W0[C0*C1];
__device__ float g_b0[C1];
__device__ float g_W1[C1*C2];
__device__ float g_b1[C2];
__device__ float g_W2[C2*C3];
__device__ float g_b2[C3];
__device__ int   g_idx[BB*SS*KK];

// ---------------- helpers ----------------
__device__ __forceinline__ unsigned long long ffma2(unsigned long long a,
                                                    unsigned long long b,
                                                    unsigned long long c) {
    unsigned long long d;
    asm("fma.rn.f32x2 %0, %1, %2, %3;" : "=l"(d) : "l"(a), "l"(b), "l"(c));
    return d;
}
__device__ __forceinline__ unsigned long long splat2(float w) {
    unsigned long long d;
    asm("mov.b64 %0, {%1, %1};" : "=l"(d) : "f"(w));
    return d;
}
__device__ __forceinline__ void unpack2(unsigned long long v, float& lo, float& hi) {
    asm("mov.b64 {%0, %1}, %2;" : "=f"(lo), "=f"(hi) : "l"(v));
}
__device__ __forceinline__ unsigned redux_max_u32(unsigned v) {
    unsigned d;
    asm("redux.sync.max.u32 %0, %1, 0xffffffff;" : "=r"(d) : "r"(v));
    return d;
}
__device__ __forceinline__ unsigned long long u64max(unsigned long long a,
                                                     unsigned long long b) {
    return a > b ? a : b;
}

// ---------------- fold BN into conv weights ----------------
__global__ void fold_kernel(const float* __restrict__ W0, const float* __restrict__ b0,
                            const float* __restrict__ g0, const float* __restrict__ be0,
                            const float* __restrict__ m0, const float* __restrict__ v0,
                            const float* __restrict__ W1, const float* __restrict__ b1,
                            const float* __restrict__ g1, const float* __restrict__ be1,
                            const float* __restrict__ m1, const float* __restrict__ v1,
                            const float* __restrict__ W2, const float* __restrict__ b2,
                            const float* __restrict__ g2, const float* __restrict__ be2,
                            const float* __restrict__ m2, const float* __restrict__ v2) {
    int o = threadIdx.x;
    if (o < C1) {
        float s = g0[o] * rsqrtf(v0[o] + 1e-5f);
        g_b0[o] = (b0[o] - m0[o]) * s + be0[o];
        for (int c = 0; c < C0; c++) g_W0[c*C1+o] = W0[c*C1+o] * s;
    }
    if (o < C2) {
        float s = g1[o] * rsqrtf(v1[o] + 1e-5f);
        g_b1[o] = (b1[o] - m1[o]) * s + be1[o];
        for (int c = 0; c < C1; c++) g_W1[c*C2+o] = W1[c*C2+o] * s;
    }
    if (o < C3) {
        float s = g2[o] * rsqrtf(v2[o] + 1e-5f);
        g_b2[o] = (b2[o] - m2[o]) * s + be2[o];
        for (int c = 0; c < C2; c++) g_W2[c*C3+o] = W2[c*C3+o] * s;
    }
}

// ---------------- farthest point sampling ----------------
// Packed u64 argmax keys: (dist_bits << 32) | ~idx.
// max(key) == (max dist, tie -> min idx)  == reference jnp.argmax semantics.
// One barrier per iteration; cross-warp reduce is a branchless 4-level u64 max tree.
#define FPS_T 512
#define PPT   8

__global__ __launch_bounds__(FPS_T) void fps_kernel(const float* __restrict__ xyz,
                                                    float* __restrict__ new_xyz) {
    extern __shared__ float fsm[];
    float* sxyz = fsm;                                          // 12288 floats
    unsigned long long* swk = (unsigned long long*)(fsm + NN*3); // [2][16]

    int b = blockIdx.x;
    const float* Xp = xyz + (size_t)b * NN * 3;
    int t = threadIdx.x;
    int lane = t & 31, w = t >> 5;

    for (int e = t; e < NN*3; e += FPS_T) sxyz[e] = Xp[e];
    __syncthreads();

    float px[PPT], py[PPT], pz[PPT], md[PPT];
#pragma unroll
    for (int i = 0; i < PPT; i++) {
        int p = t + i * FPS_T;
        px[i] = sxyz[p*3+0]; py[i] = sxyz[p*3+1]; pz[i] = sxyz[p*3+2];
        md[i] = 1e10f;
    }
    float cx = sxyz[0], cy = sxyz[1], cz = sxyz[2];
    if (t == 0) {
        new_xyz[(size_t)(b*SS)*3+0] = cx;
        new_xyz[(size_t)(b*SS)*3+1] = cy;
        new_xyz[(size_t)(b*SS)*3+2] = cz;
    }

    int par = 0;
    for (int it = 1; it < SS; it++) {
        unsigned long long best = 0ull;
#pragma unroll
        for (int i = 0; i < PPT; i++) {
            float dx = px[i]-cx, dy = py[i]-cy, dz = pz[i]-cz;
            // exact reference op order, no FMA contraction
            float d = __fadd_rn(__fadd_rn(__fmul_rn(dx,dx), __fmul_rn(dy,dy)), __fmul_rn(dz,dz));
            float m = fminf(md[i], d);
            md[i] = m;
            unsigned p = (unsigned)(t + i*FPS_T);
            unsigned long long key =
                ((unsigned long long)__float_as_uint(m) << 32) | (unsigned long long)(~p);
            best = u64max(best, key);
        }
        // warp reduce: max on high word, then max of low word among winners
        unsigned hi = (unsigned)(best >> 32);
        unsigned vmax = redux_max_u32(hi);
        unsigned lo = (hi == vmax) ? (unsigned)best : 0u;
        unsigned lmax = redux_max_u32(lo);
        if (lane == 0) swk[par*16 + w] = ((unsigned long long)vmax << 32) | lmax;
        __syncthreads();
        // branchless 16-way u64 max tree (all threads, redundant; parity buffer
        // means next iteration's writes hit the other half -> no 2nd barrier)
        unsigned long long a[16];
#pragma unroll
        for (int j = 0; j < 16; j++) a[j] = swk[par*16 + j];
#pragma unroll
        for (int j = 0; j < 8; j++) a[j] = u64max(a[j], a[j+8]);
#pragma unroll
        for (int j = 0; j < 4; j++) a[j] = u64max(a[j], a[j+4]);
        a[0] = u64max(a[0], a[2]);
        a[1] = u64max(a[1], a[3]);
        a[0] = u64max(a[0], a[1]);
        int besti = (int)(~(unsigned)a[0]);
        cx = sxyz[besti*3+0]; cy = sxyz[besti*3+1]; cz = sxyz[besti*3+2];
        if (t == 0) {
            float* op = new_xyz + (size_t)(b*SS + it)*3;
            op[0] = cx; op[1] = cy; op[2] = cz;
        }
        par ^= 1;
    }
}

// ---------------- ball query ----------------
__global__ __launch_bounds__(256) void ballquery_kernel(const float* __restrict__ xyz,
                                                        const float* __restrict__ new_xyz) {
    int gw   = (int)((blockIdx.x * blockDim.x + threadIdx.x) >> 5);
    int lane = threadIdx.x & 31;
    if (gw >= BB*SS) return;
    int b = gw >> 10;
    const float* Xp = xyz + (size_t)b * NN * 3;
    float cx = new_xyz[(size_t)gw*3+0];
    float cy = new_xyz[(size_t)gw*3+1];
    float cz = new_xyz[(size_t)gw*3+2];
    const float R2 = (float)(0.2 * 0.2);
    int* outp = g_idx + (size_t)gw * KK;
    int found = 0;
    for (int base = 0; base < NN && found < KK; base += 32) {
        int p = base + lane;
        float dx = Xp[p*3+0]-cx, dy = Xp[p*3+1]-cy, dz = Xp[p*3+2]-cz;
        float d2 = __fadd_rn(__fadd_rn(__fmul_rn(dx,dx), __fmul_rn(dy,dy)), __fmul_rn(dz,dz));
        bool pred = d2 < R2;
        unsigned m = __ballot_sync(0xffffffffu, pred);
        int pos = __popc(m & ((1u << lane) - 1u));
        if (pred && found + pos < KK) outp[found + pos] = p;
        found += __popc(m);
    }
    if (found > KK) found = KK;
    for (int j = found + lane; j < KK; j += 32) outp[j] = -1;
}

// ---------------- fused gather + 3-layer MLP + maxpool ----------------
// 8 centroids/block. X in smem [c][k] stride CP. Active-layer weights staged in a
// REUSED smem buffer with chunk-shifted layout (o + ((o>>5)<<2)) so the 8 distinct
// 16B weight reads per warp are bank-conflict-free. Thread tile 8k x 8o, FFMA2.
#define MT 256
#define WST 68          // padded weight row stride (64 data + 4 shift pad)

__device__ __forceinline__ int wpad(int o) { return o + ((o >> 5) << 2); }

// acc[i][j]: k-pairs i=0..3 (k = kb+2i, kb+2i+1), outputs j=0..7
template<int CIN>
__device__ __forceinline__ void gemm_tile(const float* __restrict__ sX, int kb,
                                          const float* __restrict__ sW, int wstride, int wo,
                                          unsigned long long acc[4][8]) {
#pragma unroll
    for (int i = 0; i < 4; i++)
#pragma unroll
        for (int j = 0; j < 8; j++) acc[i][j] = 0ull;
#pragma unroll 4
    for (int c = 0; c < CIN; c++) {
        ulonglong2 xa = *(const ulonglong2*)&sX[c*CP + kb];
        ulonglong2 xb = *(const ulonglong2*)&sX[c*CP + kb + 4];
        float4 w0 = *(const float4*)&sW[c*wstride + wo];
        float4 w1 = *(const float4*)&sW[c*wstride + wo + 4];
        unsigned long long xp[4] = {xa.x, xa.y, xb.x, xb.y};
        unsigned long long ws[8] = {splat2(w0.x), splat2(w0.y), splat2(w0.z), splat2(w0.w),
                                    splat2(w1.x), splat2(w1.y), splat2(w1.z), splat2(w1.w)};
#pragma unroll
        for (int i = 0; i < 4; i++)
#pragma unroll
            for (int j = 0; j < 8; j++) acc[i][j] = ffma2(xp[i], ws[j], acc[i][j]);
    }
}

// stage a Cx64 weight matrix into sW with padded layout
template<int CIN>
__device__ __forceinline__ void stage_w64(float* __restrict__ sW,
                                          const float* __restrict__ Wg, int t) {
    for (int e = t; e < CIN*64; e += MT) {
        int c = e >> 6, o = e & 63;
        sW[c*WST + wpad(o)] = Wg[e];
    }
}
// stage 64x128 W2 as [c][2 halves][padded 64]
__device__ __forceinline__ void stage_w128(float* __restrict__ sW,
                                           const float* __restrict__ Wg, int t) {
    for (int e = t; e < 64*128; e += MT) {
        int c = e >> 7, o = e & 127;
        int h = o >> 6, ol = o & 63;
        sW[c*(2*WST) + h*WST + wpad(ol)] = Wg[e];
    }
}

__global__ __launch_bounds__(MT, 2) void mlp_kernel(const float* __restrict__ xyz,
                                                    const float* __restrict__ points,
                                                    const float* __restrict__ new_xyz,
                                                    float* __restrict__ out_np) {
    extern __shared__ float sm[];
    float* sX   = sm;                          // 67 * CP
    float* sW   = sX + C0*CP;                  // 64 * 136 floats (reused per layer)
    int*   sMax = (int*)(sW + 64*2*WST);       // 8*128
    int*   sIdx = sMax + 8*C3;                 // 256
    float* sCent= (float*)(sIdx + 256);        // 24

    int t   = threadIdx.x;
    int bid = blockIdx.x;
    int b   = bid >> 7;
    int s0  = (bid & 127) * 8;

    sIdx[t] = g_idx[((size_t)(b*SS + s0))*KK + t];
    if (t < 24) sCent[t] = new_xyz[(size_t)(b*SS + s0)*3 + t];
#pragma unroll
    for (int q = 0; q < 4; q++) sMax[t*4 + q] = 0;  // post-ReLU >= 0
    __syncthreads();

    // gather + stage W0
    for (int e = t; e < 3*256; e += MT) {
        int c = e >> 8, k = e & 255;
        int cl = k >> 5;
        int id = sIdx[k];
        float v = (id < 0) ? 0.0f : xyz[((size_t)b*NN + id)*3 + c];
        sX[c*CP + k] = v - sCent[cl*3 + c];
    }
    for (int e = t; e < 256*16; e += MT) {
        int k = e >> 4, c4 = e & 15;
        int id = sIdx[k];
        int pid = (id < 0) ? (NN-1) : id;
        float4 p = *(const float4*)&points[((size_t)b*NN + pid)*DD + c4*4];
        sX[(3 + c4*4 + 0)*CP + k] = p.x;
        sX[(3 + c4*4 + 1)*CP + k] = p.y;
        sX[(3 + c4*4 + 2)*CP + k] = p.z;
        sX[(3 + c4*4 + 3)*CP + k] = p.w;
    }
    stage_w64<C0>(sW, g_W0, t);
    __syncthreads();

    int kb = (t >> 3) * 8;
    int ob = (t & 7) * 8;
    int wo = wpad(ob);
    unsigned long long acc[4][8];

    // ----- Layer 1: 67 -> 64 -----
    gemm_tile<C0>(sX, kb, sW, WST, wo, acc);
    __syncthreads();
#pragma unroll
    for (int j = 0; j < 8; j++) {
        int o = ob + j;
        float bb = __ldg(&g_b0[o]);
        float f[8];
#pragma unroll
        for (int i = 0; i < 4; i++) {
            float lo, hi; unpack2(acc[i][j], lo, hi);
            f[2*i]   = fmaxf(lo + bb, 0.0f);
            f[2*i+1] = fmaxf(hi + bb, 0.0f);
        }
        *(float4*)&sX[o*CP + kb]     = make_float4(f[0], f[1], f[2], f[3]);
        *(float4*)&sX[o*CP + kb + 4] = make_float4(f[4], f[5], f[6], f[7]);
    }
    stage_w64<C1>(sW, g_W1, t);
    __syncthreads();

    // ----- Layer 2: 64 -> 64 -----
    gemm_tile<C1>(sX, kb, sW, WST, wo, acc);
    __syncthreads();
#pragma unroll
    for (int j = 0; j < 8; j++) {
        int o = ob + j;
        float bb = __ldg(&g_b1[o]);
        float f[8];
#pragma unroll
        for (int i = 0; i < 4; i++) {
            float lo, hi; unpack2(acc[i][j], lo, hi);
            f[2*i]   = fmaxf(lo + bb, 0.0f);
            f[2*i+1] = fmaxf(hi + bb, 0.0f);
        }
        *(float4*)&sX[o*CP + kb]     = make_float4(f[0], f[1], f[2], f[3]);
        *(float4*)&sX[o*CP + kb + 4] = make_float4(f[4], f[5], f[6], f[7]);
    }
    stage_w128(sW, g_W2, t);
    __syncthreads();

    // ----- Layer 3: 64 -> 128 (two halves), fused maxpool -----
    int cent = kb >> 5;
#pragma unroll
    for (int h = 0; h < 2; h++) {
        gemm_tile<C2>(sX, kb, sW + h*WST, 2*WST, wo, acc);
#pragma unroll
        for (int j = 0; j < 8; j++) {
            int o = h*64 + ob + j;
            float bb = __ldg(&g_b2[o]);
            float mx = 0.0f;
#pragma unroll
            for (int i = 0; i < 4; i++) {
                float lo, hi; unpack2(acc[i][j], lo, hi);
                mx = fmaxf(mx, fmaxf(lo + bb, 0.0f));
                mx = fmaxf(mx, fmaxf(hi + bb, 0.0f));
            }
            atomicMax(&sMax[cent*C3 + o], __float_as_int(mx));
        }
    }
    __syncthreads();

    for (int e = t; e < 8*C3; e += MT) {
        int cc = e >> 7, o = e & 127;
        out_np[((size_t)(b*SS + s0 + cc))*C3 + o] = __int_as_float(sMax[e]);
    }
}

// ---------------- launch ----------------
static const size_t MLP_SMEM = (size_t)(C0*CP + 64*2*WST)*4
                             + (size_t)(8*C3 + 256)*4 + 24*4 + 16;
static const size_t FPS_SMEM = (size_t)(NN*3)*4 + 2*16*8 + 16;

extern "C" void kernel_launch(void* const* d_in, const int* in_sizes, int n_in,
                              void* d_out, int out_size) {
    const float* xyz    = (const float*)d_in[0];
    const float* points = (const float*)d_in[1];
    float* out        = (float*)d_out;
    float* new_xyz    = out;
    float* new_points = out + (size_t)BB*SS*3;

    fold_kernel<<<1, 128>>>(
        (const float*)d_in[2],  (const float*)d_in[3],  (const float*)d_in[4],
        (const float*)d_in[5],  (const float*)d_in[6],  (const float*)d_in[7],
        (const float*)d_in[8],  (const float*)d_in[9],  (const float*)d_in[10],
        (const float*)d_in[11], (const float*)d_in[12], (const float*)d_in[13],
        (const float*)d_in[14], (const float*)d_in[15], (const float*)d_in[16],
        (const float*)d_in[17], (const float*)d_in[18], (const float*)d_in[19]);

    cudaFuncSetAttribute(fps_kernel, cudaFuncAttributeMaxDynamicSharedMemorySize,
                         (int)FPS_SMEM);
    fps_kernel<<<BB, FPS_T, FPS_SMEM>>>(xyz, new_xyz);

    ballquery_kernel<<<(BB*SS*32 + 255)/256, 256>>>(xyz, new_xyz);

    cudaFuncSetAttribute(mlp_kernel, cudaFuncAttributeMaxDynamicSharedMemorySize,
                         (int)MLP_SMEM);
    mlp_kernel<<<BB*SS/8, MT, MLP_SMEM>>>(xyz, points, new_xyz, new_points);
}